// round 5
// baseline (speedup 1.0000x reference)
#include <cuda_runtime.h>

// RGCN constants
constexpr int N_   = 50000;
constexpr int E_   = 500000;
constexpr int R_   = 20;
constexpr int RT_  = 41;            // 2R+1
constexpr int B_   = 40;
constexpr int EMB_ = 16;
constexpr int C_   = 16;
constexpr int NE_  = N_ * EMB_;     // 800000
constexpr int ED_  = 2 * E_;        // directed non-loop edges
constexpr int RP_  = 21;            // r-pairs for k_w1 (last hi row dummy)
constexpr int W2R_ = 16 * 20 + 4;   // padded per-relation stride in w2t (=324)

// Scratch (static device globals)
__device__ float g_w1[(size_t)(2 * RP_) * NE_];  // 42 rows x 800000 (row 41 dummy)
__device__ float g_h[NE_];
__device__ int   g_cnt[RT_ * N_];
__device__ int   g_deg[N_];
__device__ int   g_rowptr[N_ + 1];
__device__ int   g_cursor[N_];
__device__ uint2 g_edges[ED_];                   // {(r<<16)|o, bits(v)}
__device__ float g_w2t[RT_ * W2R_];              // w2 transposed [r][e][c], padded

// ---------------------------------------------------------------------------
__global__ void k_zero() {
    int i = blockIdx.x * blockDim.x + threadIdx.x;
    if (i < RT_ * N_) g_cnt[i] = 0;
    if (i < N_) g_deg[i] = 0;
}

__global__ void k_count(const int* __restrict__ src, const int* __restrict__ dst,
                        const int* __restrict__ rel) {
    int i = blockIdx.x * blockDim.x + threadIdx.x;
    if (i >= E_) return;
    int s = src[i], d = dst[i], r = rel[i];
    atomicAdd(&g_cnt[r * N_ + s], 1);
    atomicAdd(&g_cnt[(r + R_) * N_ + d], 1);
    atomicAdd(&g_deg[s], 1);
    atomicAdd(&g_deg[d], 1);
}

// single-block exclusive scan of g_deg -> g_rowptr / g_cursor
__global__ void k_scan() {
    constexpr int T = 1024;
    constexpr int ITEMS = (N_ + T - 1) / T;   // 49
    __shared__ int sh[T];
    int t = threadIdx.x;
    int base = t * ITEMS;
    int s = 0;
    for (int i = 0; i < ITEMS; i++) {
        int idx = base + i;
        if (idx < N_) s += g_deg[idx];
    }
    sh[t] = s;
    __syncthreads();
    for (int off = 1; off < T; off <<= 1) {
        int v = (t >= off) ? sh[t - off] : 0;
        __syncthreads();
        sh[t] += v;
        __syncthreads();
    }
    int run = sh[t] - s;   // exclusive prefix
    for (int i = 0; i < ITEMS; i++) {
        int idx = base + i;
        if (idx < N_) {
            g_rowptr[idx] = run;
            g_cursor[idx] = run;
            run += g_deg[idx];
        }
    }
    if (t == T - 1) g_rowptr[N_] = sh[T - 1];
}

// pack directed edges into CSR segments: payload {(r<<16)|o, v}
__global__ void k_scatter(const int* __restrict__ src, const int* __restrict__ dst,
                          const int* __restrict__ rel) {
    int i = blockIdx.x * blockDim.x + threadIdx.x;
    if (i >= E_) return;
    int s = src[i], d = dst[i], r = rel[i];
    {
        int p = atomicAdd(&g_cursor[s], 1);
        float v = 1.0f / (float)g_cnt[r * N_ + s];
        g_edges[p] = make_uint2(((unsigned)r << 16) | (unsigned)d, __float_as_uint(v));
    }
    {
        int r2 = r + R_;
        int p = atomicAdd(&g_cursor[d], 1);
        float v = 1.0f / (float)g_cnt[r2 * N_ + d];
        g_edges[p] = make_uint2(((unsigned)r2 << 16) | (unsigned)s, __float_as_uint(v));
    }
}

// ---------------------------------------------------------------------------
// w1[r, j] = sum_b comps1[r,b] * bases1[b, j]  (packed f32x2, 2 relations/iter)
__global__ void k_w1(const float* __restrict__ comps1,
                     const float* __restrict__ bases1) {
    __shared__ unsigned long long cs2[RP_ * B_];
    for (int t = threadIdx.x; t < RP_ * B_; t += blockDim.x) {
        int p = t / B_, b = t % B_;
        float lo = comps1[(2 * p) * B_ + b];
        float hi = (2 * p + 1 < RT_) ? comps1[(2 * p + 1) * B_ + b] : 0.0f;
        unsigned long long packed;
        asm("mov.b64 %0, {%1, %2};" : "=l"(packed)
            : "r"(__float_as_uint(lo)), "r"(__float_as_uint(hi)));
        cs2[t] = packed;
    }
    __syncthreads();
    int j = blockIdx.x * blockDim.x + threadIdx.x;
    if (j >= NE_) return;

    unsigned long long dup[B_];
#pragma unroll
    for (int b = 0; b < B_; b++) {
        unsigned int v = __float_as_uint(bases1[(size_t)b * NE_ + j]);
        asm("mov.b64 %0, {%1, %1};" : "=l"(dup[b]) : "r"(v));
    }
#pragma unroll 1
    for (int p = 0; p < RP_; p++) {
        unsigned long long acc = 0ull;
        const unsigned long long* cp = &cs2[p * B_];
#pragma unroll
        for (int b = 0; b < B_; b++) {
            asm("fma.rn.f32x2 %0, %1, %2, %0;" : "+l"(acc) : "l"(cp[b]), "l"(dup[b]));
        }
        unsigned int lo, hi;
        asm("mov.b64 {%0, %1}, %2;" : "=r"(lo), "=r"(hi) : "l"(acc));
        g_w1[(size_t)(2 * p) * NE_ + j]     = __uint_as_float(lo);
        g_w1[(size_t)(2 * p + 1) * NE_ + j] = __uint_as_float(hi);  // row 41 dummy
    }
}

// w2t[r][e][c] (padded) = sum_b comps2[r,b] * bases2[b, e*16+c]
__global__ void k_w2(const float* __restrict__ comps2,
                     const float* __restrict__ bases2) {
    int i = blockIdx.x * blockDim.x + threadIdx.x;
    if (i >= RT_ * EMB_ * C_) return;
    int r = i >> 8, ec = i & 255;
    int e = ec >> 4, c = ec & 15;
    float acc = 0.0f;
#pragma unroll
    for (int b = 0; b < B_; b++)
        acc = fmaf(comps2[r * B_ + b], bases2[b * 256 + ec], acc);
    g_w2t[r * W2R_ + e * 20 + c] = acc;
}

// ---------------------------------------------------------------------------
// layer-1 gather: h[s,e] = relu( w1[40,s,e] + sum_edges v*w1[r,o,e] + bias1[e] )
// 16 lanes per node (lane = e); coalesced 64B gathers, no atomics.
__global__ void k_l1g(const float* __restrict__ bias1) {
    int tid = blockIdx.x * blockDim.x + threadIdx.x;
    int node = tid >> 4;
    int e = tid & 15;
    if (node >= N_) return;

    float acc = g_w1[(size_t)(RT_ - 1) * NE_ + node * EMB_ + e];  // self-loop, v=1
    int jb = g_rowptr[node], je = g_rowptr[node + 1];
    int j = jb;
#pragma unroll 1
    for (; j + 4 <= je; j += 4) {
        uint2 p0 = g_edges[j + 0], p1 = g_edges[j + 1];
        uint2 p2 = g_edges[j + 2], p3 = g_edges[j + 3];
        float a0 = g_w1[(size_t)(p0.x >> 16) * NE_ + (p0.x & 0xFFFFu) * EMB_ + e];
        float a1 = g_w1[(size_t)(p1.x >> 16) * NE_ + (p1.x & 0xFFFFu) * EMB_ + e];
        float a2 = g_w1[(size_t)(p2.x >> 16) * NE_ + (p2.x & 0xFFFFu) * EMB_ + e];
        float a3 = g_w1[(size_t)(p3.x >> 16) * NE_ + (p3.x & 0xFFFFu) * EMB_ + e];
        acc = fmaf(__uint_as_float(p0.y), a0, acc);
        acc = fmaf(__uint_as_float(p1.y), a1, acc);
        acc = fmaf(__uint_as_float(p2.y), a2, acc);
        acc = fmaf(__uint_as_float(p3.y), a3, acc);
    }
    for (; j < je; j++) {
        uint2 p = g_edges[j];
        float a = g_w1[(size_t)(p.x >> 16) * NE_ + (p.x & 0xFFFFu) * EMB_ + e];
        acc = fmaf(__uint_as_float(p.y), a, acc);
    }
    float x = acc + bias1[e];
    g_h[node * EMB_ + e] = fmaxf(x, 0.0f);
}

// ---------------------------------------------------------------------------
// layer-2 gather: out[s,c] = sum_edges v * sum_e h[o,e]*w2[r,e,c]
//                 + sum_e h[s,e]*w2[40,e,c] + bias2[c]
// 16 lanes per node, lane = e: per edge 1 coalesced h load + 16 FMA into
// per-lane acc[c]; cross-lane transpose-reduce once per node. No atomics.
__global__ void k_l2g(const float* __restrict__ bias2, float* __restrict__ out) {
    extern __shared__ float w2s[];
    for (int t = threadIdx.x; t < RT_ * W2R_; t += blockDim.x) w2s[t] = g_w2t[t];
    __syncthreads();

    int e = threadIdx.x & 15;
    int gstride = (gridDim.x * blockDim.x) >> 4;
    for (int node = (blockIdx.x * blockDim.x + threadIdx.x) >> 4;
         node < N_; node += gstride) {
        float acc[16];
        // self-loop: r = 40, v = 1
        {
            float hv = g_h[node * EMB_ + e];
            const float* wp = &w2s[(RT_ - 1) * W2R_ + e * 20];
            float4 A = *(const float4*)(wp);
            float4 Bv = *(const float4*)(wp + 4);
            float4 Cv = *(const float4*)(wp + 8);
            float4 Dv = *(const float4*)(wp + 12);
            acc[0] = hv * A.x;  acc[1] = hv * A.y;  acc[2] = hv * A.z;  acc[3] = hv * A.w;
            acc[4] = hv * Bv.x; acc[5] = hv * Bv.y; acc[6] = hv * Bv.z; acc[7] = hv * Bv.w;
            acc[8] = hv * Cv.x; acc[9] = hv * Cv.y; acc[10] = hv * Cv.z; acc[11] = hv * Cv.w;
            acc[12] = hv * Dv.x; acc[13] = hv * Dv.y; acc[14] = hv * Dv.z; acc[15] = hv * Dv.w;
        }
        int jb = g_rowptr[node], je = g_rowptr[node + 1];
        int j = jb;
#pragma unroll 1
        for (; j + 2 <= je; j += 2) {
            uint2 p0 = g_edges[j], p1 = g_edges[j + 1];
            float h0 = __uint_as_float(p0.y) * g_h[(p0.x & 0xFFFFu) * EMB_ + e];
            float h1 = __uint_as_float(p1.y) * g_h[(p1.x & 0xFFFFu) * EMB_ + e];
            const float* w0 = &w2s[(p0.x >> 16) * W2R_ + e * 20];
            const float* w1p = &w2s[(p1.x >> 16) * W2R_ + e * 20];
            float4 A0 = *(const float4*)(w0);      float4 B0 = *(const float4*)(w0 + 4);
            float4 C0 = *(const float4*)(w0 + 8);  float4 D0 = *(const float4*)(w0 + 12);
            float4 A1 = *(const float4*)(w1p);     float4 B1 = *(const float4*)(w1p + 4);
            float4 C1 = *(const float4*)(w1p + 8); float4 D1 = *(const float4*)(w1p + 12);
            acc[0]  = fmaf(h0, A0.x, acc[0]);  acc[1]  = fmaf(h0, A0.y, acc[1]);
            acc[2]  = fmaf(h0, A0.z, acc[2]);  acc[3]  = fmaf(h0, A0.w, acc[3]);
            acc[4]  = fmaf(h0, B0.x, acc[4]);  acc[5]  = fmaf(h0, B0.y, acc[5]);
            acc[6]  = fmaf(h0, B0.z, acc[6]);  acc[7]  = fmaf(h0, B0.w, acc[7]);
            acc[8]  = fmaf(h0, C0.x, acc[8]);  acc[9]  = fmaf(h0, C0.y, acc[9]);
            acc[10] = fmaf(h0, C0.z, acc[10]); acc[11] = fmaf(h0, C0.w, acc[11]);
            acc[12] = fmaf(h0, D0.x, acc[12]); acc[13] = fmaf(h0, D0.y, acc[13]);
            acc[14] = fmaf(h0, D0.z, acc[14]); acc[15] = fmaf(h0, D0.w, acc[15]);
            acc[0]  = fmaf(h1, A1.x, acc[0]);  acc[1]  = fmaf(h1, A1.y, acc[1]);
            acc[2]  = fmaf(h1, A1.z, acc[2]);  acc[3]  = fmaf(h1, A1.w, acc[3]);
            acc[4]  = fmaf(h1, B1.x, acc[4]);  acc[5]  = fmaf(h1, B1.y, acc[5]);
            acc[6]  = fmaf(h1, B1.z, acc[6]);  acc[7]  = fmaf(h1, B1.w, acc[7]);
            acc[8]  = fmaf(h1, C1.x, acc[8]);  acc[9]  = fmaf(h1, C1.y, acc[9]);
            acc[10] = fmaf(h1, C1.z, acc[10]); acc[11] = fmaf(h1, C1.w, acc[11]);
            acc[12] = fmaf(h1, D1.x, acc[12]); acc[13] = fmaf(h1, D1.y, acc[13]);
            acc[14] = fmaf(h1, D1.z, acc[14]); acc[15] = fmaf(h1, D1.w, acc[15]);
        }
        for (; j < je; j++) {
            uint2 p = g_edges[j];
            float hv = __uint_as_float(p.y) * g_h[(p.x & 0xFFFFu) * EMB_ + e];
            const float* wp = &w2s[(p.x >> 16) * W2R_ + e * 20];
            float4 A = *(const float4*)(wp);      float4 Bv = *(const float4*)(wp + 4);
            float4 Cv = *(const float4*)(wp + 8); float4 Dv = *(const float4*)(wp + 12);
            acc[0]  = fmaf(hv, A.x, acc[0]);   acc[1]  = fmaf(hv, A.y, acc[1]);
            acc[2]  = fmaf(hv, A.z, acc[2]);   acc[3]  = fmaf(hv, A.w, acc[3]);
            acc[4]  = fmaf(hv, Bv.x, acc[4]);  acc[5]  = fmaf(hv, Bv.y, acc[5]);
            acc[6]  = fmaf(hv, Bv.z, acc[6]);  acc[7]  = fmaf(hv, Bv.w, acc[7]);
            acc[8]  = fmaf(hv, Cv.x, acc[8]);  acc[9]  = fmaf(hv, Cv.y, acc[9]);
            acc[10] = fmaf(hv, Cv.z, acc[10]); acc[11] = fmaf(hv, Cv.w, acc[11]);
            acc[12] = fmaf(hv, Dv.x, acc[12]); acc[13] = fmaf(hv, Dv.y, acc[13]);
            acc[14] = fmaf(hv, Dv.z, acc[14]); acc[15] = fmaf(hv, Dv.w, acc[15]);
        }
        // transpose-reduce across the 16-lane group (xor <= 8 stays in group)
#pragma unroll
        for (int s = 8; s >= 1; s >>= 1) {
#pragma unroll
            for (int c = 0; c < 16; c++)
                acc[c] += __shfl_xor_sync(0xffffffffu, acc[c], s);
        }
        out[node * C_ + e] = acc[e] + bias2[e];
    }
}

// ---------------------------------------------------------------------------
extern "C" void kernel_launch(void* const* d_in, const int* in_sizes, int n_in,
                              void* d_out, int out_size) {
    const int*   src    = (const int*)d_in[0];
    const int*   dst    = (const int*)d_in[1];
    const int*   rel    = (const int*)d_in[2];
    const float* comps1 = (const float*)d_in[3];
    const float* bases1 = (const float*)d_in[4];
    const float* comps2 = (const float*)d_in[5];
    const float* bases2 = (const float*)d_in[6];
    const float* bias1  = (const float*)d_in[7];
    const float* bias2  = (const float*)d_in[8];
    float* out = (float*)d_out;

    const int T = 256;
    const int smem_l2 = RT_ * W2R_ * sizeof(float);   // ~53 KB
    cudaFuncSetAttribute(k_l2g, cudaFuncAttributeMaxDynamicSharedMemorySize, smem_l2);

    k_zero   <<<(RT_ * N_ + T - 1) / T, T>>>();
    k_count  <<<(E_ + T - 1) / T, T>>>(src, dst, rel);
    k_scan   <<<1, 1024>>>();
    k_scatter<<<(E_ + T - 1) / T, T>>>(src, dst, rel);
    k_w1     <<<(NE_ + T - 1) / T, T>>>(comps1, bases1);
    k_w2     <<<(RT_ * EMB_ * C_ + T - 1) / T, T>>>(comps2, bases2);
    k_l1g    <<<(N_ * 16 + T - 1) / T, T>>>(bias1);
    k_l2g    <<<592, T, smem_l2>>>(bias2, out);
}

// round 6
// speedup vs baseline: 1.3351x; 1.3351x over previous
#include <cuda_runtime.h>

// RGCN constants
constexpr int N_   = 50000;
constexpr int E_   = 500000;
constexpr int R_   = 20;
constexpr int RT_  = 41;            // 2R+1
constexpr int B_   = 40;
constexpr int EMB_ = 16;
constexpr int C_   = 16;
constexpr int NE_  = N_ * EMB_;     // 800000
constexpr int RP_  = 21;            // r-pairs for k_w1 (last hi row dummy)
constexpr int RC_  = RT_ * C_;      // 656 (flattened r*16+c)
constexpr int CH_  = RC_ / 4;       // 164 float4 chunks

// Scratch (static device globals)
__device__ float g_w1[(size_t)(2 * RP_) * NE_];  // [42][50000][16] (row 41 dummy)
__device__ float g_h[NE_];                       // layer-1 activations
__device__ int   g_cnt[RT_ * N_];                // per-(r,s) edge counts
__device__ float g_w2f[EMB_ * RC_];              // w2 flat [e][r*16+c]
__device__ float g_m[(size_t)N_ * RC_];          // m[o][r][c]  ~131 MB

// ---------------------------------------------------------------------------
__global__ void k_zero(float* __restrict__ out, const float* __restrict__ bias2) {
    int i = blockIdx.x * blockDim.x + threadIdx.x;
    if (i < RT_ * N_) g_cnt[i] = 0;
    if (i < NE_) out[i] = bias2[i & 15];   // bias2 pre-seeded into out
}

__global__ void k_count(const int* __restrict__ src, const int* __restrict__ dst,
                        const int* __restrict__ rel) {
    int i = blockIdx.x * blockDim.x + threadIdx.x;
    if (i >= E_) return;
    int r = rel[i];
    atomicAdd(&g_cnt[r * N_ + src[i]], 1);
    atomicAdd(&g_cnt[(r + R_) * N_ + dst[i]], 1);
}

// ---------------------------------------------------------------------------
// w1[r, j] = sum_b comps1[r,b] * bases1[b, j]  (packed f32x2, 2 relations/iter)
__global__ void k_w1(const float* __restrict__ comps1,
                     const float* __restrict__ bases1) {
    __shared__ unsigned long long cs2[RP_ * B_];
    for (int t = threadIdx.x; t < RP_ * B_; t += blockDim.x) {
        int p = t / B_, b = t % B_;
        float lo = comps1[(2 * p) * B_ + b];
        float hi = (2 * p + 1 < RT_) ? comps1[(2 * p + 1) * B_ + b] : 0.0f;
        unsigned long long packed;
        asm("mov.b64 %0, {%1, %2};" : "=l"(packed)
            : "r"(__float_as_uint(lo)), "r"(__float_as_uint(hi)));
        cs2[t] = packed;
    }
    __syncthreads();
    int j = blockIdx.x * blockDim.x + threadIdx.x;
    if (j >= NE_) return;

    unsigned long long dup[B_];
#pragma unroll
    for (int b = 0; b < B_; b++) {
        unsigned int v = __float_as_uint(bases1[(size_t)b * NE_ + j]);
        asm("mov.b64 %0, {%1, %1};" : "=l"(dup[b]) : "r"(v));
    }
#pragma unroll 1
    for (int p = 0; p < RP_; p++) {
        unsigned long long acc = 0ull;
        const unsigned long long* cp = &cs2[p * B_];
#pragma unroll
        for (int b = 0; b < B_; b++) {
            asm("fma.rn.f32x2 %0, %1, %2, %0;" : "+l"(acc) : "l"(cp[b]), "l"(dup[b]));
        }
        unsigned int lo, hi;
        asm("mov.b64 {%0, %1}, %2;" : "=r"(lo), "=r"(hi) : "l"(acc));
        g_w1[(size_t)(2 * p) * NE_ + j]     = __uint_as_float(lo);
        g_w1[(size_t)(2 * p + 1) * NE_ + j] = __uint_as_float(hi);  // row 41 dummy
    }
}

// ---------------------------------------------------------------------------
// layer-1 scatter: h[s,:] += v * w1[r, o, :].  4 threads/edge, one RED.v4 each.
__global__ void k_l1(const int* __restrict__ src, const int* __restrict__ dst,
                     const int* __restrict__ rel) {
    int idx = blockIdx.x * blockDim.x + threadIdx.x;
    if (idx >= 2 * E_ * 4) return;
    int q  = idx & 3;
    int e2 = idx >> 2;
    int s, o, r;
    if (e2 < E_) { s = src[e2]; o = dst[e2]; r = rel[e2]; }
    else         { int e = e2 - E_; s = dst[e]; o = src[e]; r = rel[e] + R_; }
    float v = 1.0f / (float)g_cnt[r * N_ + s];
    const float4 w = *(const float4*)&g_w1[(size_t)r * NE_ + o * EMB_ + q * 4];
    float* hp = &g_h[s * EMB_ + q * 4];
    asm volatile("red.global.add.v4.f32 [%0], {%1, %2, %3, %4};"
                 :: "l"(hp), "f"(v * w.x), "f"(v * w.y), "f"(v * w.z), "f"(v * w.w)
                 : "memory");
}

// h starts as the accumulated edge sums (g_h zeroed by first-touch? no — must init!)
// NOTE: g_h must be zeroed before k_l1; done in k_zero2 below.
__global__ void k_zero2() {
    int i = blockIdx.x * blockDim.x + threadIdx.x;
    if (i < NE_) g_h[i] = 0.0f;
}

// self-loop (v=1) + bias + relu
__global__ void k_relu(const float* __restrict__ bias1) {
    int j = blockIdx.x * blockDim.x + threadIdx.x;
    if (j >= NE_) return;
    float x = g_h[j] + g_w1[(size_t)(RT_ - 1) * NE_ + j] + bias1[j & 15];
    g_h[j] = fmaxf(x, 0.0f);
}

// w2 flat: w2f[e][r*16+c] = sum_b comps2[r,b] * bases2[b, e*16+c]
__global__ void k_w2(const float* __restrict__ comps2,
                     const float* __restrict__ bases2) {
    int i = blockIdx.x * blockDim.x + threadIdx.x;
    if (i >= RT_ * EMB_ * C_) return;
    int r = i >> 8, ec = i & 255;
    int e = ec >> 4, c = ec & 15;
    float acc = 0.0f;
#pragma unroll
    for (int b = 0; b < B_; b++)
        acc = fmaf(comps2[r * B_ + b], bases2[b * 256 + ec], acc);
    g_w2f[e * RC_ + r * 16 + c] = acc;
}

// ---------------------------------------------------------------------------
// m[o][rc] = sum_e h[o,e] * w2f[e][rc].  Persistent blocks; each warp-class
// holds its 32 float4 w2 chunks in REGISTERS (64 regs/lane); h via shfl.
__global__ void __launch_bounds__(192) k_mgemm() {
    int w    = threadIdx.x >> 5;          // warp-class 0..5
    int lane = threadIdx.x & 31;
    int chunk = w * 32 + lane;            // rc4 chunk id
    bool act = chunk < CH_;
    int ch = act ? chunk : 0;

    float4 w2r[EMB_];
#pragma unroll
    for (int e = 0; e < EMB_; e++)
        w2r[e] = *(const float4*)&g_w2f[e * RC_ + ch * 4];

    int node = blockIdx.x;
    float hval = (node < N_) ? g_h[node * EMB_ + (lane & 15)] : 0.0f;
    for (; node < N_; node += gridDim.x) {
        int nxt = node + gridDim.x;
        float hnext = (nxt < N_) ? g_h[nxt * EMB_ + (lane & 15)] : 0.0f;
        float4 acc = make_float4(0.f, 0.f, 0.f, 0.f);
#pragma unroll
        for (int e = 0; e < EMB_; e++) {
            float he = __shfl_sync(0xffffffffu, hval, e);
            acc.x = fmaf(he, w2r[e].x, acc.x);
            acc.y = fmaf(he, w2r[e].y, acc.y);
            acc.z = fmaf(he, w2r[e].z, acc.z);
            acc.w = fmaf(he, w2r[e].w, acc.w);
        }
        if (act) *(float4*)&g_m[(size_t)node * RC_ + chunk * 4] = acc;
        hval = hnext;
    }
}

// ---------------------------------------------------------------------------
// layer-2 edge pass (clone of k_l1): out[s,:] += v * m[o][r][:]
__global__ void k_l2e(const int* __restrict__ src, const int* __restrict__ dst,
                      const int* __restrict__ rel, float* __restrict__ out) {
    int idx = blockIdx.x * blockDim.x + threadIdx.x;
    if (idx >= 2 * E_ * 4) return;
    int q  = idx & 3;
    int e2 = idx >> 2;
    int s, o, r;
    if (e2 < E_) { s = src[e2]; o = dst[e2]; r = rel[e2]; }
    else         { int e = e2 - E_; s = dst[e]; o = src[e]; r = rel[e] + R_; }
    float v = 1.0f / (float)g_cnt[r * N_ + s];
    const float4 w = *(const float4*)&g_m[(size_t)o * RC_ + r * 16 + q * 4];
    float* op = &out[s * C_ + q * 4];
    asm volatile("red.global.add.v4.f32 [%0], {%1, %2, %3, %4};"
                 :: "l"(op), "f"(v * w.x), "f"(v * w.y), "f"(v * w.z), "f"(v * w.w)
                 : "memory");
}

// self-loop of layer 2: out[n,c] += m[n][40][c]   (bias2 already seeded)
__global__ void k_fin(float* __restrict__ out) {
    int j = blockIdx.x * blockDim.x + threadIdx.x;
    if (j >= NE_) return;
    int n = j >> 4, c = j & 15;
    out[j] += g_m[(size_t)n * RC_ + (RT_ - 1) * 16 + c];
}

// ---------------------------------------------------------------------------
extern "C" void kernel_launch(void* const* d_in, const int* in_sizes, int n_in,
                              void* d_out, int out_size) {
    const int*   src    = (const int*)d_in[0];
    const int*   dst    = (const int*)d_in[1];
    const int*   rel    = (const int*)d_in[2];
    const float* comps1 = (const float*)d_in[3];
    const float* bases1 = (const float*)d_in[4];
    const float* comps2 = (const float*)d_in[5];
    const float* bases2 = (const float*)d_in[6];
    const float* bias1  = (const float*)d_in[7];
    const float* bias2  = (const float*)d_in[8];
    float* out = (float*)d_out;

    const int T = 256;
    k_zero  <<<(RT_ * N_ + T - 1) / T, T>>>(out, bias2);
    k_zero2 <<<(NE_ + T - 1) / T, T>>>();
    k_count <<<(E_ + T - 1) / T, T>>>(src, dst, rel);
    k_w1    <<<(NE_ + T - 1) / T, T>>>(comps1, bases1);
    k_w2    <<<(RT_ * EMB_ * C_ + T - 1) / T, T>>>(comps2, bases2);
    k_l1    <<<(2 * E_ * 4 + T - 1) / T, T>>>(src, dst, rel);
    k_relu  <<<(NE_ + T - 1) / T, T>>>(bias1);
    k_mgemm <<<444, 192>>>();
    k_l2e   <<<(2 * E_ * 4 + T - 1) / T, T>>>(src, dst, rel, out);
    k_fin   <<<(NE_ + T - 1) / T, T>>>(out);
}

// round 7
// speedup vs baseline: 1.3422x; 1.0053x over previous
#include <cuda_runtime.h>

// RGCN constants
constexpr int N_   = 50000;
constexpr int E_   = 500000;
constexpr int R_   = 20;
constexpr int RT_  = 41;            // 2R+1
constexpr int B_   = 40;
constexpr int EMB_ = 16;
constexpr int C_   = 16;
constexpr int NE_  = N_ * EMB_;     // 800000
constexpr int RC_  = RT_ * C_;      // 656 (flattened r*16+c)
constexpr int CH_  = RC_ / 4;       // 164 float4 chunks
constexpr int JP_  = NE_ / 2;       // 400000 j-pairs

// Scratch (static device globals)
__device__ float g_w1[(size_t)RT_ * NE_];        // [41][50000][16]
__device__ float g_h[NE_];                       // layer-1 activations
__device__ int   g_cnt[RT_ * N_];                // per-(r,s) edge counts
__device__ float g_w2f[EMB_ * RC_];              // w2 flat [e][r*16+c]
__device__ float g_m[(size_t)N_ * RC_];          // m[o][r][c]  ~131 MB

// ---------------------------------------------------------------------------
__global__ void k_zero(float* __restrict__ out, const float* __restrict__ bias2) {
    int i = blockIdx.x * blockDim.x + threadIdx.x;
    if (i < RT_ * N_) g_cnt[i] = 0;
    if (i < NE_) { g_h[i] = 0.0f; out[i] = bias2[i & 15]; }
}

__global__ void k_count(const int* __restrict__ src, const int* __restrict__ dst,
                        const int* __restrict__ rel) {
    int i = blockIdx.x * blockDim.x + threadIdx.x;
    if (i >= E_) return;
    int r = rel[i];
    atomicAdd(&g_cnt[r * N_ + src[i]], 1);
    atomicAdd(&g_cnt[(r + R_) * N_ + dst[i]], 1);
}

// ---------------------------------------------------------------------------
// w1[r, j] = sum_b comps1[r,b] * bases1[b, j]
// f32x2 packed over a j-PAIR per thread; bases held in 80 registers
// (launch_bounds grants 128 regs); comps pre-duplicated {c,c} in smem.
// Inner loop = 1 LDS.64 + 1 FFMA2 per (r,b): fma & lsu pipes co-saturate.
__global__ void __launch_bounds__(128, 4) k_w1(const float* __restrict__ comps1,
                                               const float* __restrict__ bases1) {
    __shared__ unsigned long long cs2[RT_ * B_];   // {c,c} per (r,b), 13.1 KB
    for (int t = threadIdx.x; t < RT_ * B_; t += 128) {
        unsigned int c = __float_as_uint(comps1[t]);
        unsigned long long packed;
        asm("mov.b64 %0, {%1, %1};" : "=l"(packed) : "r"(c));
        cs2[t] = packed;
    }
    __syncthreads();

    int jp = blockIdx.x * 128 + threadIdx.x;       // j-pair index
    if (jp >= JP_) return;

    unsigned long long bp[B_];                     // 40 x float2 = 80 regs
#pragma unroll
    for (int b = 0; b < B_; b++)
        bp[b] = *(const unsigned long long*)&bases1[(size_t)b * NE_ + 2 * jp];

#pragma unroll 1
    for (int r = 0; r < RT_ - 1; r += 2) {         // 2 chains in flight
        const unsigned long long* c0 = &cs2[r * B_];
        const unsigned long long* c1 = &cs2[(r + 1) * B_];
        unsigned long long a0 = 0ull, a1 = 0ull;
#pragma unroll
        for (int b = 0; b < B_; b++) {
            asm("fma.rn.f32x2 %0, %1, %2, %0;" : "+l"(a0) : "l"(bp[b]), "l"(c0[b]));
            asm("fma.rn.f32x2 %0, %1, %2, %0;" : "+l"(a1) : "l"(bp[b]), "l"(c1[b]));
        }
        *(unsigned long long*)&g_w1[(size_t)r * NE_ + 2 * jp] = a0;
        *(unsigned long long*)&g_w1[(size_t)(r + 1) * NE_ + 2 * jp] = a1;
    }
    {   // last relation (r = 40)
        const unsigned long long* c0 = &cs2[(RT_ - 1) * B_];
        unsigned long long a0 = 0ull;
#pragma unroll
        for (int b = 0; b < B_; b++)
            asm("fma.rn.f32x2 %0, %1, %2, %0;" : "+l"(a0) : "l"(bp[b]), "l"(c0[b]));
        *(unsigned long long*)&g_w1[(size_t)(RT_ - 1) * NE_ + 2 * jp] = a0;
    }
}

// ---------------------------------------------------------------------------
// layer-1 scatter: h[s,:] += v * w1[r, o, :].  4 threads/edge, one RED.v4 each.
__global__ void k_l1(const int* __restrict__ src, const int* __restrict__ dst,
                     const int* __restrict__ rel) {
    int idx = blockIdx.x * blockDim.x + threadIdx.x;
    if (idx >= 2 * E_ * 4) return;
    int q  = idx & 3;
    int e2 = idx >> 2;
    int s, o, r;
    if (e2 < E_) { s = src[e2]; o = dst[e2]; r = rel[e2]; }
    else         { int e = e2 - E_; s = dst[e]; o = src[e]; r = rel[e] + R_; }
    float v = 1.0f / (float)g_cnt[r * N_ + s];
    const float4 w = *(const float4*)&g_w1[(size_t)r * NE_ + o * EMB_ + q * 4];
    float* hp = &g_h[s * EMB_ + q * 4];
    asm volatile("red.global.add.v4.f32 [%0], {%1, %2, %3, %4};"
                 :: "l"(hp), "f"(v * w.x), "f"(v * w.y), "f"(v * w.z), "f"(v * w.w)
                 : "memory");
}

// self-loop (v=1) + bias + relu
__global__ void k_relu(const float* __restrict__ bias1) {
    int j = blockIdx.x * blockDim.x + threadIdx.x;
    if (j >= NE_) return;
    float x = g_h[j] + g_w1[(size_t)(RT_ - 1) * NE_ + j] + bias1[j & 15];
    g_h[j] = fmaxf(x, 0.0f);
}

// w2 flat: w2f[e][r*16+c] = sum_b comps2[r,b] * bases2[b, e*16+c]
__global__ void k_w2(const float* __restrict__ comps2,
                     const float* __restrict__ bases2) {
    int i = blockIdx.x * blockDim.x + threadIdx.x;
    if (i >= RT_ * EMB_ * C_) return;
    int r = i >> 8, ec = i & 255;
    int e = ec >> 4, c = ec & 15;
    float acc = 0.0f;
#pragma unroll
    for (int b = 0; b < B_; b++)
        acc = fmaf(comps2[r * B_ + b], bases2[b * 256 + ec], acc);
    g_w2f[e * RC_ + r * 16 + c] = acc;
}

// ---------------------------------------------------------------------------
// m[o][rc] = sum_e h[o,e] * w2f[e][rc].  Persistent blocks; each warp-class
// holds its 32 float4 w2 chunks in REGISTERS (64 regs/lane); h via shfl.
__global__ void __launch_bounds__(192) k_mgemm() {
    int w    = threadIdx.x >> 5;          // warp-class 0..5
    int lane = threadIdx.x & 31;
    int chunk = w * 32 + lane;            // rc4 chunk id
    bool act = chunk < CH_;
    int ch = act ? chunk : 0;

    float4 w2r[EMB_];
#pragma unroll
    for (int e = 0; e < EMB_; e++)
        w2r[e] = *(const float4*)&g_w2f[e * RC_ + ch * 4];

    int node = blockIdx.x;
    float hval = (node < N_) ? g_h[node * EMB_ + (lane & 15)] : 0.0f;
    for (; node < N_; node += gridDim.x) {
        int nxt = node + gridDim.x;
        float hnext = (nxt < N_) ? g_h[nxt * EMB_ + (lane & 15)] : 0.0f;
        float4 acc = make_float4(0.f, 0.f, 0.f, 0.f);
#pragma unroll
        for (int e = 0; e < EMB_; e++) {
            float he = __shfl_sync(0xffffffffu, hval, e);
            acc.x = fmaf(he, w2r[e].x, acc.x);
            acc.y = fmaf(he, w2r[e].y, acc.y);
            acc.z = fmaf(he, w2r[e].z, acc.z);
            acc.w = fmaf(he, w2r[e].w, acc.w);
        }
        if (act) *(float4*)&g_m[(size_t)node * RC_ + chunk * 4] = acc;
        hval = hnext;
    }
}

// ---------------------------------------------------------------------------
// layer-2 edge pass (clone of k_l1): out[s,:] += v * m[o][r][:]
__global__ void k_l2e(const int* __restrict__ src, const int* __restrict__ dst,
                      const int* __restrict__ rel, float* __restrict__ out) {
    int idx = blockIdx.x * blockDim.x + threadIdx.x;
    if (idx >= 2 * E_ * 4) return;
    int q  = idx & 3;
    int e2 = idx >> 2;
    int s, o, r;
    if (e2 < E_) { s = src[e2]; o = dst[e2]; r = rel[e2]; }
    else         { int e = e2 - E_; s = dst[e]; o = src[e]; r = rel[e] + R_; }
    float v = 1.0f / (float)g_cnt[r * N_ + s];
    const float4 w = *(const float4*)&g_m[(size_t)o * RC_ + r * 16 + q * 4];
    float* op = &out[s * C_ + q * 4];
    asm volatile("red.global.add.v4.f32 [%0], {%1, %2, %3, %4};"
                 :: "l"(op), "f"(v * w.x), "f"(v * w.y), "f"(v * w.z), "f"(v * w.w)
                 : "memory");
}

// self-loop of layer 2: out[n,c] += m[n][40][c]   (bias2 already seeded)
__global__ void k_fin(float* __restrict__ out) {
    int j = blockIdx.x * blockDim.x + threadIdx.x;
    if (j >= NE_) return;
    int n = j >> 4, c = j & 15;
    out[j] += g_m[(size_t)n * RC_ + (RT_ - 1) * 16 + c];
}

// ---------------------------------------------------------------------------
extern "C" void kernel_launch(void* const* d_in, const int* in_sizes, int n_in,
                              void* d_out, int out_size) {
    const int*   src    = (const int*)d_in[0];
    const int*   dst    = (const int*)d_in[1];
    const int*   rel    = (const int*)d_in[2];
    const float* comps1 = (const float*)d_in[3];
    const float* bases1 = (const float*)d_in[4];
    const float* comps2 = (const float*)d_in[5];
    const float* bases2 = (const float*)d_in[6];
    const float* bias1  = (const float*)d_in[7];
    const float* bias2  = (const float*)d_in[8];
    float* out = (float*)d_out;

    const int T = 256;
    k_zero  <<<(RT_ * N_ + T - 1) / T, T>>>(out, bias2);
    k_count <<<(E_ + T - 1) / T, T>>>(src, dst, rel);
    k_w1    <<<(JP_ + 127) / 128, 128>>>(comps1, bases1);
    k_w2    <<<(RT_ * EMB_ * C_ + T - 1) / T, T>>>(comps2, bases2);
    k_l1    <<<(2 * E_ * 4 + T - 1) / T, T>>>(src, dst, rel);
    k_relu  <<<(NE_ + T - 1) / T, T>>>(bias1);
    k_mgemm <<<444, 192>>>();
    k_l2e   <<<(2 * E_ * 4 + T - 1) / T, T>>>(src, dst, rel, out);
    k_fin   <<<(NE_ + T - 1) / T, T>>>(out);
}

// round 8
// speedup vs baseline: 1.3749x; 1.0243x over previous
#include <cuda_runtime.h>

// RGCN constants
constexpr int N_   = 50000;
constexpr int E_   = 500000;
constexpr int R_   = 20;
constexpr int RT_  = 41;            // 2R+1
constexpr int B_   = 40;
constexpr int EMB_ = 16;
constexpr int C_   = 16;
constexpr int NE_  = N_ * EMB_;     // 800000
constexpr int RC_  = RT_ * C_;      // 656 (flattened r*16+c)
constexpr int CH_  = RC_ / 4;       // 164 float4 chunks
constexpr int JP_  = NE_ / 2;       // 400000 j-pairs
constexpr int WB_  = (JP_ + 127) / 128;          // w1 blocks  (3125)
constexpr int CB_  = (E_ + 127) / 128;           // count blocks (3907)

// Scratch (static device globals)
__device__ float g_w1[(size_t)RT_ * NE_];        // [41][50000][16]
__device__ float g_h[NE_];                       // layer-1 pre-activations
__device__ int   g_cnt[RT_ * N_];                // per-(r,s) edge counts
__device__ float g_w2f[EMB_ * RC_];              // w2 flat [e][r*16+c]
__device__ float g_m[(size_t)N_ * RC_];          // m[o][r][c]  ~131 MB

// ---------------------------------------------------------------------------
// pre-pass: zero cnt & h, seed out with bias2, compute w2f. One launch.
__global__ void k_pre(float* __restrict__ out, const float* __restrict__ bias2,
                      const float* __restrict__ comps2,
                      const float* __restrict__ bases2) {
    int i = blockIdx.x * blockDim.x + threadIdx.x;
    if (i < RT_ * N_) g_cnt[i] = 0;
    if (i < NE_) { g_h[i] = 0.0f; out[i] = bias2[i & 15]; }
    if (i < RT_ * EMB_ * C_) {
        int r = i >> 8, ec = i & 255;
        int e = ec >> 4, c = ec & 15;
        float acc = 0.0f;
#pragma unroll
        for (int b = 0; b < B_; b++)
            acc = fmaf(comps2[r * B_ + b], bases2[b * 256 + ec], acc);
        g_w2f[e * RC_ + r * 16 + c] = acc;
    }
}

// ---------------------------------------------------------------------------
// Fused: blocks [0,WB_) compute w1 = comps1 x bases1 (f32x2 over j-pairs,
// comps quad-packed so one LDS.128 feeds two FFMA2); blocks [WB_, WB_+CB_)
// do the per-(r,s) edge counting (atomics overlap the GEMM).
__global__ void __launch_bounds__(128, 4) k_w1c(const float* __restrict__ comps1,
                                                const float* __restrict__ bases1,
                                                const int* __restrict__ src,
                                                const int* __restrict__ dst,
                                                const int* __restrict__ rel) {
    if (blockIdx.x >= WB_) {
        int i = (blockIdx.x - WB_) * 128 + threadIdx.x;
        if (i < E_) {
            int r = rel[i];
            atomicAdd(&g_cnt[r * N_ + src[i]], 1);
            atomicAdd(&g_cnt[(r + R_) * N_ + dst[i]], 1);
        }
        return;
    }

    // {c[2k],c[2k], c[2k+1],c[2k+1]} quads: 41 rows x 20 quads, 13.1 KB
    __shared__ __align__(16) ulonglong2 cs4[RT_ * (B_ / 2)];
    for (int t = threadIdx.x; t < RT_ * B_; t += 128) {
        int r = t / B_, b = t % B_;
        unsigned int c = __float_as_uint(comps1[t]);
        unsigned long long packed;
        asm("mov.b64 %0, {%1, %1};" : "=l"(packed) : "r"(c));
        ((unsigned long long*)cs4)[r * B_ + b] = packed;
    }
    __syncthreads();

    int jp = blockIdx.x * 128 + threadIdx.x;       // j-pair index
    if (jp >= JP_) return;

    unsigned long long bp[B_];                     // 40 x float2 = 80 regs
#pragma unroll
    for (int b = 0; b < B_; b++)
        bp[b] = *(const unsigned long long*)&bases1[(size_t)b * NE_ + 2 * jp];

#pragma unroll 1
    for (int r = 0; r < RT_ - 1; r += 2) {         // 2 chains in flight
        const ulonglong2* c0 = &cs4[r * (B_ / 2)];
        const ulonglong2* c1 = &cs4[(r + 1) * (B_ / 2)];
        unsigned long long a0 = 0ull, a1 = 0ull;
#pragma unroll
        for (int k = 0; k < B_ / 2; k++) {
            ulonglong2 q0 = c0[k];                 // LDS.128 -> 2 comps pairs
            ulonglong2 q1 = c1[k];
            asm("fma.rn.f32x2 %0, %1, %2, %0;" : "+l"(a0) : "l"(bp[2*k]),   "l"(q0.x));
            asm("fma.rn.f32x2 %0, %1, %2, %0;" : "+l"(a0) : "l"(bp[2*k+1]), "l"(q0.y));
            asm("fma.rn.f32x2 %0, %1, %2, %0;" : "+l"(a1) : "l"(bp[2*k]),   "l"(q1.x));
            asm("fma.rn.f32x2 %0, %1, %2, %0;" : "+l"(a1) : "l"(bp[2*k+1]), "l"(q1.y));
        }
        *(unsigned long long*)&g_w1[(size_t)r * NE_ + 2 * jp] = a0;
        *(unsigned long long*)&g_w1[(size_t)(r + 1) * NE_ + 2 * jp] = a1;
    }
    {   // last relation (r = 40)
        const ulonglong2* c0 = &cs4[(RT_ - 1) * (B_ / 2)];
        unsigned long long a0 = 0ull;
#pragma unroll
        for (int k = 0; k < B_ / 2; k++) {
            ulonglong2 q0 = c0[k];
            asm("fma.rn.f32x2 %0, %1, %2, %0;" : "+l"(a0) : "l"(bp[2*k]),   "l"(q0.x));
            asm("fma.rn.f32x2 %0, %1, %2, %0;" : "+l"(a0) : "l"(bp[2*k+1]), "l"(q0.y));
        }
        *(unsigned long long*)&g_w1[(size_t)(RT_ - 1) * NE_ + 2 * jp] = a0;
    }
}

// ---------------------------------------------------------------------------
// layer-1 scatter: h[s,:] += v * w1[r, o, :].  4 threads/edge, one RED.v4 each.
__global__ void k_l1(const int* __restrict__ src, const int* __restrict__ dst,
                     const int* __restrict__ rel) {
    int idx = blockIdx.x * blockDim.x + threadIdx.x;
    if (idx >= 2 * E_ * 4) return;
    int q  = idx & 3;
    int e2 = idx >> 2;
    int s, o, r;
    if (e2 < E_) { s = src[e2]; o = dst[e2]; r = rel[e2]; }
    else         { int e = e2 - E_; s = dst[e]; o = src[e]; r = rel[e] + R_; }
    float v = 1.0f / (float)g_cnt[r * N_ + s];
    const float4 w = *(const float4*)&g_w1[(size_t)r * NE_ + o * EMB_ + q * 4];
    float* hp = &g_h[s * EMB_ + q * 4];
    asm volatile("red.global.add.v4.f32 [%0], {%1, %2, %3, %4};"
                 :: "l"(hp), "f"(v * w.x), "f"(v * w.y), "f"(v * w.z), "f"(v * w.w)
                 : "memory");
}

// ---------------------------------------------------------------------------
// m[o][rc] = sum_e relu(h[o,e]+w1[40,o,e]+bias1[e]) * w2f[e][rc]
// (layer-1 epilogue fused into the h load). w2 chunks in registers; h via shfl.
__global__ void __launch_bounds__(192) k_mgemm(const float* __restrict__ bias1) {
    int w    = threadIdx.x >> 5;          // warp-class 0..5
    int lane = threadIdx.x & 31;
    int le   = lane & 15;
    int chunk = w * 32 + lane;            // rc4 chunk id
    bool act = chunk < CH_;
    int ch = act ? chunk : 0;

    float4 w2r[EMB_];
#pragma unroll
    for (int e = 0; e < EMB_; e++)
        w2r[e] = *(const float4*)&g_w2f[e * RC_ + ch * 4];
    float breg = bias1[le];
    const float* w1sl = &g_w1[(size_t)(RT_ - 1) * NE_];

    int node = blockIdx.x;
    float hval = 0.0f;
    if (node < N_)
        hval = fmaxf(g_h[node * EMB_ + le] + w1sl[node * EMB_ + le] + breg, 0.0f);
    for (; node < N_; node += gridDim.x) {
        int nxt = node + gridDim.x;
        float hnext = 0.0f;
        if (nxt < N_)
            hnext = fmaxf(g_h[nxt * EMB_ + le] + w1sl[nxt * EMB_ + le] + breg, 0.0f);
        float4 acc = make_float4(0.f, 0.f, 0.f, 0.f);
#pragma unroll
        for (int e = 0; e < EMB_; e++) {
            float he = __shfl_sync(0xffffffffu, hval, e);
            acc.x = fmaf(he, w2r[e].x, acc.x);
            acc.y = fmaf(he, w2r[e].y, acc.y);
            acc.z = fmaf(he, w2r[e].z, acc.z);
            acc.w = fmaf(he, w2r[e].w, acc.w);
        }
        if (act) *(float4*)&g_m[(size_t)node * RC_ + chunk * 4] = acc;
        hval = hnext;
    }
}

// ---------------------------------------------------------------------------
// layer-2 edge pass incl. self-loop pseudo-edges: out[s,:] += v * m[o][r][:]
__global__ void k_l2e(const int* __restrict__ src, const int* __restrict__ dst,
                      const int* __restrict__ rel, float* __restrict__ out) {
    int idx = blockIdx.x * blockDim.x + threadIdx.x;
    if (idx >= (2 * E_ + N_) * 4) return;
    int q  = idx & 3;
    int e2 = idx >> 2;
    int s, o, r;
    float v;
    if (e2 < E_) {
        s = src[e2]; o = dst[e2]; r = rel[e2];
        v = 1.0f / (float)g_cnt[r * N_ + s];
    } else if (e2 < 2 * E_) {
        int e = e2 - E_;
        s = dst[e]; o = src[e]; r = rel[e] + R_;
        v = 1.0f / (float)g_cnt[r * N_ + s];
    } else {
        int n = e2 - 2 * E_;
        s = n; o = n; r = RT_ - 1; v = 1.0f;
    }
    const float4 w = *(const float4*)&g_m[(size_t)o * RC_ + r * 16 + q * 4];
    float* op = &out[s * C_ + q * 4];
    asm volatile("red.global.add.v4.f32 [%0], {%1, %2, %3, %4};"
                 :: "l"(op), "f"(v * w.x), "f"(v * w.y), "f"(v * w.z), "f"(v * w.w)
                 : "memory");
}

// ---------------------------------------------------------------------------
extern "C" void kernel_launch(void* const* d_in, const int* in_sizes, int n_in,
                              void* d_out, int out_size) {
    const int*   src    = (const int*)d_in[0];
    const int*   dst    = (const int*)d_in[1];
    const int*   rel    = (const int*)d_in[2];
    const float* comps1 = (const float*)d_in[3];
    const float* bases1 = (const float*)d_in[4];
    const float* comps2 = (const float*)d_in[5];
    const float* bases2 = (const float*)d_in[6];
    const float* bias1  = (const float*)d_in[7];
    const float* bias2  = (const float*)d_in[8];
    float* out = (float*)d_out;

    const int T = 256;
    k_pre   <<<(RT_ * N_ + T - 1) / T, T>>>(out, bias2, comps2, bases2);
    k_w1c   <<<WB_ + CB_, 128>>>(comps1, bases1, src, dst, rel);
    k_l1    <<<(2 * E_ * 4 + T - 1) / T, T>>>(src, dst, rel);
    k_mgemm <<<444, 192>>>(bias1);
    k_l2e   <<<((2 * E_ + N_) * 4 + T - 1) / T, T>>>(src, dst, rel, out);
}